// round 1
// baseline (speedup 1.0000x reference)
#include <cuda_runtime.h>
#include <math.h>

#define BB 4
#define CINc 256
#define EMBc 64
#define HH 64
#define WW 64
#define HO 128
#define WO 128
#define KKc 25

// ---------------- scratch (static device globals; no allocations) ----------------
__device__ float g_enc[BB*EMBc*HO*WO];    // compressed en  (4,64,128,128)
__device__ float g_dec[BB*EMBc*HH*WW];    // compressed de  (4,64,64,64)
__device__ float g_gate[BB*HH*WW];        // sigmoid gate at source res
__device__ float g_len[BB*KKc*HO*WO];     // conv3x3(enc) logits
__device__ float g_lde[BB*KKc*HH*WW];     // conv3x3(dec) logits
__device__ float g_wenT[CINc*EMBc];       // w_cen transposed [c][o]
__device__ float g_wdeT[CINc*EMBc];       // w_cde transposed [c][o]
__device__ float g_wceR[EMBc*9*28];       // w_ce reordered [c][q][o pad28]

// ---------------- prep: weight transposes (tiny) ----------------
__global__ void k_prep(const float* __restrict__ w_cen,
                       const float* __restrict__ w_cde,
                       const float* __restrict__ w_ce) {
    int i = blockIdx.x * 256 + threadIdx.x;
    if (i < EMBc*CINc) {
        int o = i >> 8, c = i & 255;
        g_wenT[c*EMBc + o] = w_cen[i];
        g_wdeT[c*EMBc + o] = w_cde[i];
    }
    if (i < KKc*EMBc*9) {
        int o = i / (EMBc*9);
        int r = i - o*(EMBc*9);
        int c = r / 9;
        int q = r - c*9;
        g_wceR[(c*9 + q)*28 + o] = w_ce[i];
    }
}

// ---------------- 1x1 compress GEMM: out[b,o,p] = sum_c w[o,c]*in[b,c,p] (+bias) ----------------
// block: 256 threads, tile 64 outputs x 128 pixels. Full W (256x64) staged in smem.
template<bool BIAS, bool GATE>
__global__ __launch_bounds__(256) void k_compress(
    const float* __restrict__ in, const float* __restrict__ wT,
    const float* __restrict__ bias, float* __restrict__ out,
    const float* __restrict__ gw, const float* __restrict__ gb,
    float* __restrict__ gate_out, int Npix)
{
    extern __shared__ float sm[];
    float* w_s  = sm;                   // [256][64]
    float* in_s = sm + CINc*EMBc;       // [2][8][128]
    float* gw_s = in_s + 2048;          // [256]

    int tid = threadIdx.x;
    int b   = blockIdx.y;
    int p0  = blockIdx.x * 128;
    const float* inb = in + (size_t)b*CINc*Npix + p0;

    for (int i = tid; i < CINc*EMBc; i += 256) w_s[i] = wT[i];
    if (GATE) gw_s[tid] = gw[tid];

    int scc = tid >> 5;
    int sj  = (tid & 31) << 2;
    *(float4*)&in_s[scc*128 + sj] = *(const float4*)&inb[(size_t)scc*Npix + sj];
    __syncthreads();

    int og = (tid >> 5) << 3;   // output base
    int pj = (tid & 31) << 2;   // pixel base
    float acc[8][4];
    #pragma unroll
    for (int o = 0; o < 8; ++o)
        #pragma unroll
        for (int j = 0; j < 4; ++j) acc[o][j] = 0.0f;
    float gacc[4] = {0.f,0.f,0.f,0.f};

    int buf = 0;
    for (int c0 = 0; c0 < CINc; c0 += 8) {
        if (c0 + 8 < CINc)
            *(float4*)&in_s[(buf^1)*1024 + scc*128 + sj] =
                *(const float4*)&inb[(size_t)(c0+8+scc)*Npix + sj];
        const float* ib = &in_s[buf*1024];
        #pragma unroll
        for (int cc = 0; cc < 8; ++cc) {
            float4 w0 = *(const float4*)&w_s[(c0+cc)*EMBc + og];
            float4 w1 = *(const float4*)&w_s[(c0+cc)*EMBc + og + 4];
            float4 iv = *(const float4*)&ib[cc*128 + pj];
            float wv[8] = {w0.x,w0.y,w0.z,w0.w,w1.x,w1.y,w1.z,w1.w};
            float pv[4] = {iv.x,iv.y,iv.z,iv.w};
            #pragma unroll
            for (int o = 0; o < 8; ++o)
                #pragma unroll
                for (int j = 0; j < 4; ++j)
                    acc[o][j] += wv[o]*pv[j];
            if (GATE) {
                if (og == 0) {
                    float gv = gw_s[c0+cc];
                    #pragma unroll
                    for (int j = 0; j < 4; ++j) gacc[j] += gv*pv[j];
                }
            }
        }
        __syncthreads();
        buf ^= 1;
    }

    #pragma unroll
    for (int o = 0; o < 8; ++o) {
        float bo = BIAS ? bias[og+o] : 0.0f;
        float4 r;
        r.x = acc[o][0]+bo; r.y = acc[o][1]+bo; r.z = acc[o][2]+bo; r.w = acc[o][3]+bo;
        *(float4*)&out[((size_t)b*EMBc + og + o)*Npix + p0 + pj] = r;
    }
    if (GATE) {
        if (og == 0) {
            float gb0 = gb[0];
            #pragma unroll
            for (int j = 0; j < 4; ++j) {
                float z = gacc[j] + gb0;
                gate_out[(size_t)b*Npix + p0 + pj + j] = 1.0f/(1.0f + __expf(-z));
            }
        }
    }
}

// ---------------- 3x3 conv, 64 -> 25 channels, pad=1 ----------------
// block: 128 threads, tile 8 rows x 32 cols, thread = 2 px, 25 outputs.
__global__ __launch_bounds__(128) void k_conv3(
    const float* __restrict__ in, const float* __restrict__ bias,
    float* __restrict__ out, int Hn, int Wn)
{
    __shared__ __align__(16) float in_s[8][10][36];
    __shared__ __align__(16) float w_s[8][9][28];
    int b  = blockIdx.z;
    int x0 = blockIdx.x << 5;
    int y0 = blockIdx.y << 3;
    int tid = threadIdx.x;
    int tx = tid & 15, ty = tid >> 4;

    float acc0[KKc], acc1[KKc];
    #pragma unroll
    for (int o = 0; o < KKc; ++o) { acc0[o] = 0.f; acc1[o] = 0.f; }

    for (int c0 = 0; c0 < EMBc; c0 += 8) {
        __syncthreads();
        for (int idx = tid; idx < 8*10*34; idx += 128) {
            int col = idx % 34; int t = idx / 34; int row = t % 10; int cc = t / 10;
            int gy = y0 - 1 + row, gx = x0 - 1 + col;
            float v = 0.0f;
            if (gy >= 0 && gy < Hn && gx >= 0 && gx < Wn)
                v = in[(((size_t)b*EMBc + c0 + cc)*Hn + gy)*Wn + gx];
            in_s[cc][row][col] = v;
        }
        for (int idx = tid; idx < 8*9*KKc; idx += 128) {
            int o = idx % KKc; int t = idx / KKc; int q = t % 9; int cc = t / 9;
            w_s[cc][q][o] = g_wceR[((c0+cc)*9 + q)*28 + o];
        }
        __syncthreads();
        #pragma unroll 2
        for (int cc = 0; cc < 8; ++cc) {
            #pragma unroll
            for (int dy = 0; dy < 3; ++dy) {
                float2 pa = *(const float2*)&in_s[cc][ty+dy][tx*2];
                float2 pb = *(const float2*)&in_s[cc][ty+dy][tx*2 + 2];
                float iv[4] = {pa.x, pa.y, pb.x, pb.y};
                #pragma unroll
                for (int dx = 0; dx < 3; ++dx) {
                    const float* wp = w_s[cc][dy*3+dx];
                    float va = iv[dx], vb = iv[dx+1];
                    #pragma unroll
                    for (int o4 = 0; o4 < 24; o4 += 4) {
                        float4 wv = *(const float4*)&wp[o4];
                        acc0[o4+0] += wv.x*va; acc1[o4+0] += wv.x*vb;
                        acc0[o4+1] += wv.y*va; acc1[o4+1] += wv.y*vb;
                        acc0[o4+2] += wv.z*va; acc1[o4+2] += wv.z*vb;
                        acc0[o4+3] += wv.w*va; acc1[o4+3] += wv.w*vb;
                    }
                    float w24 = wp[24];
                    acc0[24] += w24*va; acc1[24] += w24*vb;
                }
            }
        }
    }
    int y = y0 + ty, x = x0 + tx*2;
    #pragma unroll
    for (int o = 0; o < KKc; ++o) {
        float bo = bias[o];
        float2 r; r.x = acc0[o]+bo; r.y = acc1[o]+bo;
        *(float2*)&out[(((size_t)b*KKc + o)*Hn + y)*Wn + x] = r;
    }
}

// ---------------- fused softmax + CARAFE + gate blend ----------------
// thread = one source pixel (y,x) -> 2x2 output quad; block covers 64 channels (grid.z packs b,cgroup)
__global__ __launch_bounds__(128) void k_fuse(
    const float* __restrict__ en, const float* __restrict__ de,
    float* __restrict__ out)
{
    __shared__ float de_s[8][8][36];
    int x0 = blockIdx.x << 5;
    int y0 = blockIdx.y << 2;
    int bz = blockIdx.z; int b = bz >> 2; int cg = (bz & 3) << 6;
    int tid = threadIdx.x;
    int lx = tid & 31, ly = tid >> 5;
    int y = y0 + ly, x = x0 + lx;

    float g = g_gate[((size_t)b*HH + y)*WW + x];
    float ldv[KKc];
    #pragma unroll
    for (int k = 0; k < KKc; ++k)
        ldv[k] = g_lde[(((size_t)b*KKc + k)*HH + y)*WW + x];

    float wgt[4][KKc];
    #pragma unroll
    for (int px = 0; px < 4; ++px) {
        int iy = 2*y + (px >> 1), ix = 2*x + (px & 1);
        const float* lp = g_len + ((size_t)b*KKc*HO + iy)*WO + ix;
        float m = -1e30f;
        #pragma unroll
        for (int k = 0; k < KKc; ++k) {
            float l = lp[(size_t)k*HO*WO] + ldv[k];
            wgt[px][k] = l;
            m = fmaxf(m, l);
        }
        float s = 0.0f;
        #pragma unroll
        for (int k = 0; k < KKc; ++k) {
            float e = __expf(wgt[px][k] - m);
            wgt[px][k] = e; s += e;
        }
        float r = (1.0f - g) / s;
        #pragma unroll
        for (int k = 0; k < KKc; ++k) wgt[px][k] *= r;
    }

    for (int c0 = 0; c0 < 64; c0 += 8) {
        __syncthreads();
        for (int idx = tid; idx < 8*8*36; idx += 128) {
            int col = idx % 36; int t = idx / 36; int row = t & 7; int cc = t >> 3;
            int gy = y0 - 2 + row, gx = x0 - 2 + col;
            float v = 0.0f;
            if (gy >= 0 && gy < HH && gx >= 0 && gx < WW)
                v = de[(((size_t)b*CINc + cg + c0 + cc)*HH + gy)*WW + gx];
            de_s[cc][row][col] = v;
        }
        __syncthreads();
        #pragma unroll
        for (int cc = 0; cc < 8; ++cc) {
            int c = cg + c0 + cc;
            float a0=0.f, a1=0.f, a2=0.f, a3=0.f;
            #pragma unroll
            for (int dy = 0; dy < 5; ++dy)
                #pragma unroll
                for (int dx = 0; dx < 5; ++dx) {
                    float v = de_s[cc][ly+dy][lx+dx];
                    int k = dy*5+dx;
                    a0 += wgt[0][k]*v;
                    a1 += wgt[1][k]*v;
                    a2 += wgt[2][k]*v;
                    a3 += wgt[3][k]*v;
                }
            size_t base = (((size_t)b*CINc + c)*HO + 2*y)*WO + 2*x;
            float2 e0 = *(const float2*)&en[base];
            float2 e1 = *(const float2*)&en[base + WO];
            float2 r0; r0.x = g*e0.x + a0; r0.y = g*e0.y + a1;
            float2 r1; r1.x = g*e1.x + a2; r1.y = g*e1.y + a3;
            *(float2*)&out[base] = r0;
            *(float2*)&out[base + WO] = r1;
        }
    }
}

// ---------------- host launcher ----------------
extern "C" void kernel_launch(void* const* d_in, const int* in_sizes, int n_in,
                              void* d_out, int out_size) {
    const float* en     = (const float*)d_in[0];
    const float* de     = (const float*)d_in[1];
    const float* w_gate = (const float*)d_in[2];
    const float* b_gate = (const float*)d_in[3];
    const float* w_cen  = (const float*)d_in[4];
    const float* b_cen  = (const float*)d_in[5];
    const float* w_cde  = (const float*)d_in[6];
    const float* w_ce   = (const float*)d_in[7];
    const float* b_ce   = (const float*)d_in[8];
    float* out = (float*)d_out;

    float *p_enc, *p_dec, *p_gate, *p_len, *p_lde, *p_wen, *p_wde;
    cudaGetSymbolAddress((void**)&p_enc,  g_enc);
    cudaGetSymbolAddress((void**)&p_dec,  g_dec);
    cudaGetSymbolAddress((void**)&p_gate, g_gate);
    cudaGetSymbolAddress((void**)&p_len,  g_len);
    cudaGetSymbolAddress((void**)&p_lde,  g_lde);
    cudaGetSymbolAddress((void**)&p_wen,  g_wenT);
    cudaGetSymbolAddress((void**)&p_wde,  g_wdeT);

    int smemA = (CINc*EMBc + 2*1024 + 256) * (int)sizeof(float);
    cudaFuncSetAttribute(k_compress<true,false>,
                         cudaFuncAttributeMaxDynamicSharedMemorySize, smemA);
    cudaFuncSetAttribute(k_compress<false,true>,
                         cudaFuncAttributeMaxDynamicSharedMemorySize, smemA);

    k_prep<<<64, 256>>>(w_cen, w_cde, w_ce);

    k_compress<true,false><<<dim3(HO*WO/128, BB), 256, smemA>>>(
        en, p_wen, b_cen, p_enc, nullptr, nullptr, nullptr, HO*WO);

    k_compress<false,true><<<dim3(HH*WW/128, BB), 256, smemA>>>(
        de, p_wde, nullptr, p_dec, w_gate, b_gate, p_gate, HH*WW);

    k_conv3<<<dim3(WO/32, HO/8, BB), 128>>>(p_enc, b_ce, p_len, HO, WO);
    k_conv3<<<dim3(WW/32, HH/8, BB), 128>>>(p_dec, b_ce, p_lde, HH, WW);

    k_fuse<<<dim3(WW/32, HH/4, BB*4), 128>>>(en, de, out);
}

// round 3
// speedup vs baseline: 1.0940x; 1.0940x over previous
#include <cuda_runtime.h>
#include <math.h>

#define BB 4
#define CINc 256
#define EMBc 64
#define HH 64
#define WW 64
#define HO 128
#define WO 128
#define KKc 25

typedef unsigned long long ull;

__device__ __forceinline__ ull pack2(float x, float y) {
    ull d; asm("mov.b64 %0, {%1, %2};" : "=l"(d) : "f"(x), "f"(y)); return d;
}
__device__ __forceinline__ void unpack2(float& x, float& y, ull d) {
    asm("mov.b64 {%0, %1}, %2;" : "=f"(x), "=f"(y) : "l"(d));
}
__device__ __forceinline__ ull ffma2(ull a, ull b, ull c) {
    ull d; asm("fma.rn.f32x2 %0, %1, %2, %3;" : "=l"(d) : "l"(a), "l"(b), "l"(c)); return d;
}

// ---------------- scratch ----------------
__device__ float g_enc[BB*EMBc*HO*WO];
__device__ float g_dec[BB*EMBc*HH*WW];
__device__ float g_gate[BB*HH*WW];
__device__ float g_len[2*BB*KKc*HO*WO];   // two K-split halves
__device__ float g_lde[2*BB*KKc*HH*WW];
__device__ float g_wenT[CINc*EMBc];
__device__ float g_wdeT[CINc*EMBc];
__device__ float g_wceR[EMBc*9*28];

// ---------------- prep ----------------
__global__ void k_prep(const float* __restrict__ w_cen,
                       const float* __restrict__ w_cde,
                       const float* __restrict__ w_ce) {
    int i = blockIdx.x * 256 + threadIdx.x;
    if (i < EMBc*CINc) {
        int o = i >> 8, c = i & 255;
        g_wenT[c*EMBc + o] = w_cen[i];
        g_wdeT[c*EMBc + o] = w_cde[i];
    }
    if (i < KKc*EMBc*9) {
        int o = i / (EMBc*9);
        int r = i - o*(EMBc*9);
        int c = r / 9;
        int q = r - c*9;
        g_wceR[(c*9 + q)*28 + o] = w_ce[i];
    }
}

// ---------------- merged 1x1 compress (en + de jobs), FFMA2 ----------------
// 256 threads, tile 64 out x 256 px, thread = 8 out x 8 px (two dense 4-px halves)
__global__ __launch_bounds__(256) void k_compress2(
    const float* __restrict__ en, const float* __restrict__ de,
    const float* __restrict__ w_gate, const float* __restrict__ b_gate,
    const float* __restrict__ b_cen)
{
    extern __shared__ float sm[];
    float* w_s  = sm;            // 16384 floats
    float* in_s = sm + 16384;    // 2 x 2048
    float* gw_s = sm + 20480;    // 256

    int z = blockIdx.z;
    bool is_en = (z < 4);
    int b = is_en ? z : z - 4;
    if (!is_en && blockIdx.x >= 16) return;
    int Npix = is_en ? HO*WO : HH*WW;
    const float* in  = is_en ? en : de;
    const float* wT  = is_en ? g_wenT : g_wdeT;
    float* out       = is_en ? g_enc : g_dec;

    int tid = threadIdx.x;
    int p0  = blockIdx.x * 256;
    const float* inb = in + (size_t)b*CINc*Npix + p0;

    {
        const float4* src = (const float4*)wT;
        float4* dst = (float4*)w_s;
        for (int i = tid; i < 4096; i += 256) dst[i] = src[i];
    }
    if (!is_en) gw_s[tid] = w_gate[tid];

    int scc = tid >> 5;
    int sj4 = (tid & 31) << 2;
    *(float4*)&in_s[scc*256 + sj4]       = *(const float4*)&inb[(size_t)scc*Npix + sj4];
    *(float4*)&in_s[scc*256 + 128 + sj4] = *(const float4*)&inb[(size_t)scc*Npix + 128 + sj4];
    __syncthreads();

    int og = (tid >> 5) << 3;
    int pj = (tid & 31) << 2;

    ull acc2[4][8];
    #pragma unroll
    for (int op = 0; op < 4; ++op)
        #pragma unroll
        for (int j = 0; j < 8; ++j) acc2[op][j] = 0ull;
    float gacc[8] = {0.f,0.f,0.f,0.f,0.f,0.f,0.f,0.f};

    int buf = 0;
    for (int c0 = 0; c0 < CINc; c0 += 8) {
        if (c0 + 8 < CINc) {
            int c = c0 + 8 + scc;
            *(float4*)&in_s[(buf^1)*2048 + scc*256 + sj4] =
                *(const float4*)&inb[(size_t)c*Npix + sj4];
            *(float4*)&in_s[(buf^1)*2048 + scc*256 + 128 + sj4] =
                *(const float4*)&inb[(size_t)c*Npix + 128 + sj4];
        }
        const float* ib = &in_s[buf*2048];
        #pragma unroll
        for (int cc = 0; cc < 8; ++cc) {
            const ulonglong2* wp = (const ulonglong2*)&w_s[(c0+cc)*EMBc + og];
            ulonglong2 wA = wp[0], wB = wp[1];
            ull wv[4] = {wA.x, wA.y, wB.x, wB.y};
            float4 pA = *(const float4*)&ib[cc*256 + pj];
            float4 pB = *(const float4*)&ib[cc*256 + 128 + pj];
            ull p2[8];
            p2[0]=pack2(pA.x,pA.x); p2[1]=pack2(pA.y,pA.y);
            p2[2]=pack2(pA.z,pA.z); p2[3]=pack2(pA.w,pA.w);
            p2[4]=pack2(pB.x,pB.x); p2[5]=pack2(pB.y,pB.y);
            p2[6]=pack2(pB.z,pB.z); p2[7]=pack2(pB.w,pB.w);
            #pragma unroll
            for (int op = 0; op < 4; ++op)
                #pragma unroll
                for (int j = 0; j < 8; ++j)
                    acc2[op][j] = ffma2(wv[op], p2[j], acc2[op][j]);
            if (!is_en && og == 0) {
                float gv = gw_s[c0+cc];
                gacc[0]+=gv*pA.x; gacc[1]+=gv*pA.y; gacc[2]+=gv*pA.z; gacc[3]+=gv*pA.w;
                gacc[4]+=gv*pB.x; gacc[5]+=gv*pB.y; gacc[6]+=gv*pB.z; gacc[7]+=gv*pB.w;
            }
        }
        __syncthreads();
        buf ^= 1;
    }

    #pragma unroll
    for (int op = 0; op < 4; ++op) {
        int o0 = og + 2*op, o1 = o0 + 1;
        float b0 = 0.f, b1 = 0.f;
        if (is_en) { b0 = b_cen[o0]; b1 = b_cen[o1]; }
        float lo[8], hi[8];
        #pragma unroll
        for (int j = 0; j < 8; ++j) unpack2(lo[j], hi[j], acc2[op][j]);
        float4 r;
        r = make_float4(lo[0]+b0, lo[1]+b0, lo[2]+b0, lo[3]+b0);
        *(float4*)&out[((size_t)b*EMBc + o0)*Npix + p0 + pj] = r;
        r = make_float4(lo[4]+b0, lo[5]+b0, lo[6]+b0, lo[7]+b0);
        *(float4*)&out[((size_t)b*EMBc + o0)*Npix + p0 + 128 + pj] = r;
        r = make_float4(hi[0]+b1, hi[1]+b1, hi[2]+b1, hi[3]+b1);
        *(float4*)&out[((size_t)b*EMBc + o1)*Npix + p0 + pj] = r;
        r = make_float4(hi[4]+b1, hi[5]+b1, hi[6]+b1, hi[7]+b1);
        *(float4*)&out[((size_t)b*EMBc + o1)*Npix + p0 + 128 + pj] = r;
    }
    if (!is_en && og == 0) {
        float gb0 = b_gate[0];
        float4 r;
        r.x = 1.f/(1.f+__expf(-(gacc[0]+gb0)));
        r.y = 1.f/(1.f+__expf(-(gacc[1]+gb0)));
        r.z = 1.f/(1.f+__expf(-(gacc[2]+gb0)));
        r.w = 1.f/(1.f+__expf(-(gacc[3]+gb0)));
        *(float4*)&g_gate[(size_t)b*Npix + p0 + pj] = r;
        r.x = 1.f/(1.f+__expf(-(gacc[4]+gb0)));
        r.y = 1.f/(1.f+__expf(-(gacc[5]+gb0)));
        r.z = 1.f/(1.f+__expf(-(gacc[6]+gb0)));
        r.w = 1.f/(1.f+__expf(-(gacc[7]+gb0)));
        *(float4*)&g_gate[(size_t)b*Npix + p0 + 128 + pj] = r;
    }
}

// ---------------- merged 3x3 conv (hi + lo), split-K over channels, FFMA2 ----------------
// 256 threads, tile 8 rows x 32 cols, 1 px/thread, 25 outputs
__global__ __launch_bounds__(256) void k_conv3m(const float* __restrict__ bias)
{
    __shared__ __align__(16) float in_s[8][10][34];
    __shared__ __align__(16) float w_s[8][9][28];
    int z = blockIdx.z;
    const float* in; float* out; int Hn, Wn, b, half;
    if (z < 8) {
        b = z >> 1; half = z & 1;
        in = g_enc; out = g_len + (size_t)half*BB*KKc*HO*WO; Hn = HO; Wn = WO;
    } else {
        int t = z - 8; b = t >> 1; half = t & 1;
        if (blockIdx.x >= 2 || blockIdx.y >= 8) return;
        in = g_dec; out = g_lde + (size_t)half*BB*KKc*HH*WW; Hn = HH; Wn = WW;
    }
    int x0 = blockIdx.x << 5, y0 = blockIdx.y << 3;
    int tid = threadIdx.x, tx = tid & 31, ty = tid >> 5;
    int cbase = half << 5;

    ull acc2[12]; float acc24 = 0.f;
    #pragma unroll
    for (int j = 0; j < 12; ++j) acc2[j] = 0ull;

    for (int c0 = cbase; c0 < cbase + 32; c0 += 8) {
        __syncthreads();
        for (int idx = tid; idx < 8*10*34; idx += 256) {
            int col = idx % 34; int t2 = idx / 34; int row = t2 % 10; int cc = t2 / 10;
            int gy = y0 - 1 + row, gx = x0 - 1 + col;
            float v = 0.f;
            if (gy >= 0 && gy < Hn && gx >= 0 && gx < Wn)
                v = in[(((size_t)b*EMBc + c0 + cc)*Hn + gy)*Wn + gx];
            in_s[cc][row][col] = v;
        }
        for (int idx = tid; idx < 8*9*KKc; idx += 256) {
            int o = idx % KKc; int t2 = idx / KKc; int q = t2 % 9; int cc = t2 / 9;
            w_s[cc][q][o] = g_wceR[((c0+cc)*9 + q)*28 + o];
        }
        __syncthreads();
        #pragma unroll 2
        for (int cc = 0; cc < 8; ++cc) {
            #pragma unroll
            for (int dy = 0; dy < 3; ++dy) {
                float r0 = in_s[cc][ty+dy][tx];
                float r1 = in_s[cc][ty+dy][tx+1];
                float r2 = in_s[cc][ty+dy][tx+2];
                float rr[3] = {r0, r1, r2};
                #pragma unroll
                for (int dx = 0; dx < 3; ++dx) {
                    ull va2 = pack2(rr[dx], rr[dx]);
                    const ulonglong2* wp = (const ulonglong2*)&w_s[cc][dy*3+dx][0];
                    ulonglong2 wA = wp[0], wB = wp[1], wC = wp[2];
                    ulonglong2 wD = wp[3], wE = wp[4], wF = wp[5];
                    acc2[0]  = ffma2(wA.x, va2, acc2[0]);
                    acc2[1]  = ffma2(wA.y, va2, acc2[1]);
                    acc2[2]  = ffma2(wB.x, va2, acc2[2]);
                    acc2[3]  = ffma2(wB.y, va2, acc2[3]);
                    acc2[4]  = ffma2(wC.x, va2, acc2[4]);
                    acc2[5]  = ffma2(wC.y, va2, acc2[5]);
                    acc2[6]  = ffma2(wD.x, va2, acc2[6]);
                    acc2[7]  = ffma2(wD.y, va2, acc2[7]);
                    acc2[8]  = ffma2(wE.x, va2, acc2[8]);
                    acc2[9]  = ffma2(wE.y, va2, acc2[9]);
                    acc2[10] = ffma2(wF.x, va2, acc2[10]);
                    acc2[11] = ffma2(wF.y, va2, acc2[11]);
                    acc24 += w_s[cc][dy*3+dx][24] * rr[dx];
                }
            }
        }
    }
    int y = y0 + ty, x = x0 + tx;
    #pragma unroll
    for (int j = 0; j < 12; ++j) {
        float lo, hi;
        unpack2(lo, hi, acc2[j]);
        int o0 = 2*j;
        float b0 = (half == 0) ? bias[o0]   : 0.f;
        float b1 = (half == 0) ? bias[o0+1] : 0.f;
        out[(((size_t)b*KKc + o0  )*Hn + y)*Wn + x] = lo + b0;
        out[(((size_t)b*KKc + o0+1)*Hn + y)*Wn + x] = hi + b1;
    }
    {
        float b24 = (half == 0) ? bias[24] : 0.f;
        out[(((size_t)b*KKc + 24)*Hn + y)*Wn + x] = acc24 + b24;
    }
}

// ---------------- fused softmax + CARAFE + gate blend (two-phase, cg=32) ----------------
__global__ __launch_bounds__(128) void k_fuse(
    const float* __restrict__ en, const float* __restrict__ de,
    float* __restrict__ out)
{
    __shared__ float de_s[8][8][36];
    int x0 = blockIdx.x << 5, y0 = blockIdx.y << 2;
    int bz = blockIdx.z; int b = bz >> 3; int cg = (bz & 7) << 5;
    int tid = threadIdx.x;
    int lx = tid & 31, ly = tid >> 5;
    int y = y0 + ly, x = x0 + lx;

    float g = g_gate[((size_t)b*HH + y)*WW + x];
    const float* lde0 = g_lde + (size_t)b*KKc*HH*WW + y*WW + x;
    const float* lde1 = lde0 + (size_t)BB*KKc*HH*WW;
    float ldv[KKc];
    #pragma unroll
    for (int k = 0; k < KKc; ++k)
        ldv[k] = lde0[(size_t)k*HH*WW] + lde1[(size_t)k*HH*WW];

    for (int ph = 0; ph < 2; ++ph) {
        int iy = 2*y + ph;
        const float* lp0 = g_len + ((size_t)b*KKc*HO + iy)*WO + 2*x;
        const float* lp1 = lp0 + (size_t)BB*KKc*HO*WO;
        float w0[KKc], w1[KKc];
        float m0 = -1e30f, m1 = -1e30f;
        #pragma unroll
        for (int k = 0; k < KKc; ++k) {
            float2 a = *(const float2*)&lp0[(size_t)k*HO*WO];
            float2 c = *(const float2*)&lp1[(size_t)k*HO*WO];
            float l0 = a.x + c.x + ldv[k];
            float l1 = a.y + c.y + ldv[k];
            w0[k] = l0; w1[k] = l1;
            m0 = fmaxf(m0, l0); m1 = fmaxf(m1, l1);
        }
        float s0 = 0.f, s1 = 0.f;
        #pragma unroll
        for (int k = 0; k < KKc; ++k) {
            float e0 = __expf(w0[k] - m0); w0[k] = e0; s0 += e0;
            float e1 = __expf(w1[k] - m1); w1[k] = e1; s1 += e1;
        }
        float r0 = (1.f - g) / s0, r1 = (1.f - g) / s1;
        #pragma unroll
        for (int k = 0; k < KKc; ++k) { w0[k] *= r0; w1[k] *= r1; }

        for (int c0 = 0; c0 < 32; c0 += 8) {
            __syncthreads();
            for (int idx = tid; idx < 8*8*36; idx += 128) {
                int col = idx % 36; int t2 = idx / 36; int row = t2 & 7; int cc = t2 >> 3;
                int gy = y0 - 2 + row, gx = x0 - 2 + col;
                float v = 0.f;
                if (gy >= 0 && gy < HH && gx >= 0 && gx < WW)
                    v = de[(((size_t)b*CINc + cg + c0 + cc)*HH + gy)*WW + gx];
                de_s[cc][row][col] = v;
            }
            __syncthreads();
            #pragma unroll
            for (int cc = 0; cc < 8; ++cc) {
                float a0 = 0.f, a1 = 0.f;
                #pragma unroll
                for (int dy = 0; dy < 5; ++dy)
                    #pragma unroll
                    for (int dx = 0; dx < 5; ++dx) {
                        float v = de_s[cc][ly+dy][lx+dx];
                        int k = dy*5 + dx;
                        a0 += w0[k]*v; a1 += w1[k]*v;
                    }
                size_t base = (((size_t)b*CINc + cg + c0 + cc)*HO + iy)*WO + 2*x;
                float2 e = *(const float2*)&en[base];
                float2 r; r.x = g*e.x + a0; r.y = g*e.y + a1;
                *(float2*)&out[base] = r;
            }
        }
    }
}

// ---------------- host launcher ----------------
extern "C" void kernel_launch(void* const* d_in, const int* in_sizes, int n_in,
                              void* d_out, int out_size) {
    const float* en     = (const float*)d_in[0];
    const float* de     = (const float*)d_in[1];
    const float* w_gate = (const float*)d_in[2];
    const float* b_gate = (const float*)d_in[3];
    const float* w_cen  = (const float*)d_in[4];
    const float* b_cen  = (const float*)d_in[5];
    const float* w_cde  = (const float*)d_in[6];
    const float* w_ce   = (const float*)d_in[7];
    const float* b_ce   = (const float*)d_in[8];
    float* out = (float*)d_out;

    int smemC = 20736 * (int)sizeof(float);
    cudaFuncSetAttribute(k_compress2,
                         cudaFuncAttributeMaxDynamicSharedMemorySize, smemC);

    k_prep<<<64, 256>>>(w_cen, w_cde, w_ce);
    k_compress2<<<dim3(64, 1, 8), 256, smemC>>>(en, de, w_gate, b_gate, b_cen);
    k_conv3m<<<dim3(4, 16, 16), 256>>>(b_ce);
    k_fuse<<<dim3(2, 16, 32), 128>>>(en, de, out);
}